// round 1
// baseline (speedup 1.0000x reference)
#include <cuda_runtime.h>
#include <math.h>

#define BB 65536
#define KK 256
#define DD 128

// ---- scratch (static device globals; no allocation) ----
__device__ float g_K[(size_t)BB * KK];   // K' = exp(-C/eps) + 1e-8   (64MB)
__device__ float g_C[(size_t)BB * KK];   // C = 1 - cos               (64MB)
__device__ float g_ynT[DD * KK];         // normalized prototypes, k-major [k][j]
__device__ float g_xinv[BB];             // 1 / ||x_i||
__device__ float g_a[BB];                // exp(u)
__device__ float g_T[3][KK * 32];        // column sums, padded: element j at j*32 (128B apart)
__device__ double g_sum;

// ---------------------------------------------------------------------------
// init: normalize prototypes (transposed store), init T ping-pong, zero sum
// ---------------------------------------------------------------------------
__global__ void k_init(const float* __restrict__ proto) {
    int j = threadIdx.x;  // 0..255
    float ss = 0.f;
#pragma unroll 8
    for (int k = 0; k < DD; k++) { float v = proto[j * DD + k]; ss += v * v; }
    float inv = __fdividef(1.f, fmaxf(sqrtf(ss), 1e-12f));
    for (int k = 0; k < DD; k++) g_ynT[k * KK + j] = proto[j * DD + k] * inv;
    const float nuP = 1.f / (float)KK + 1e-8f;
    g_T[0][j * 32] = nuP;   // makes w == 1 on iteration 1 (v0 = 0)
    g_T[1][j * 32] = 0.f;   // accumulation target of iteration 1
    if (j == 0) g_sum = 0.0;
}

// ---------------------------------------------------------------------------
// x row inverse norms (warp per row)
// ---------------------------------------------------------------------------
__global__ void k_xnorm(const float* __restrict__ x) {
    int warp = threadIdx.x >> 5, lane = threadIdx.x & 31;
    int row = blockIdx.x * 8 + warp;
    float4 v = ((const float4*)(x + (size_t)row * DD))[lane];
    float ss = v.x * v.x + v.y * v.y + v.z * v.z + v.w * v.w;
#pragma unroll
    for (int o = 16; o; o >>= 1) ss += __shfl_xor_sync(0xffffffffu, ss, o);
    if (lane == 0) g_xinv[row] = __fdividef(1.f, fmaxf(sqrtf(ss), 1e-12f));
}

// ---------------------------------------------------------------------------
// cost GEMM: C = 1 - (x/||x||) . ynT, K' = exp(-C/eps) + 1e-8
// block = 256 threads, 64 rows x 256 cols per block, 8x8 register tile/thread
// ---------------------------------------------------------------------------
__global__ void k_gemm(const float* __restrict__ x) {
    __shared__ float ys[32 * 256];  // k-chunk of prototypes [kk][col]  (32KB)
    __shared__ float xs[64 * 32];   // x tile [row][kk]                 (8KB)
    __shared__ float xrn[64];

    int t = threadIdx.x;
    int rowBase = blockIdx.x * 64;
    if (t < 64) xrn[t] = g_xinv[rowBase + t];

    int tx = t & 31, ty = t >> 5;  // tx: 8-col group, ty: 8-row group
    float acc[8][8];
#pragma unroll
    for (int i = 0; i < 8; i++)
#pragma unroll
        for (int j = 0; j < 8; j++) acc[i][j] = 0.f;

    for (int kc = 0; kc < 4; kc++) {
        __syncthreads();
        {   // load ys chunk (k-major, fully coalesced)
            const float4* src = (const float4*)(g_ynT + kc * 32 * 256);
            float4* dst = (float4*)ys;
#pragma unroll
            for (int i = 0; i < 8; i++) dst[t + i * 256] = src[t + i * 256];
        }
        {   // load xs chunk
#pragma unroll
            for (int i = 0; i < 2; i++) {
                int idx = t + i * 256;       // float4 slot 0..511
                int r = idx >> 3;
                int c4 = idx & 7;
                float4 v = *(const float4*)(x + (size_t)(rowBase + r) * DD + kc * 32 + c4 * 4);
                *(float4*)&xs[r * 32 + c4 * 4] = v;
            }
        }
        __syncthreads();
#pragma unroll 4
        for (int k = 0; k < 32; k++) {
            float4 b0 = *(const float4*)&ys[k * 256 + tx * 8];
            float4 b1 = *(const float4*)&ys[k * 256 + tx * 8 + 4];
#pragma unroll
            for (int i = 0; i < 8; i++) {
                float a = xs[(ty * 8 + i) * 32 + k];   // broadcast LDS
                acc[i][0] += a * b0.x; acc[i][1] += a * b0.y;
                acc[i][2] += a * b0.z; acc[i][3] += a * b0.w;
                acc[i][4] += a * b1.x; acc[i][5] += a * b1.y;
                acc[i][6] += a * b1.z; acc[i][7] += a * b1.w;
            }
        }
    }

#pragma unroll
    for (int i = 0; i < 8; i++) {
        int row = rowBase + ty * 8 + i;
        float inv = xrn[ty * 8 + i];
        float c[8], kv[8];
#pragma unroll
        for (int j = 0; j < 8; j++) {
            c[j] = 1.f - acc[i][j] * inv;
            kv[j] = __expf(-10.f * c[j]) + 1e-8f;
        }
        size_t base = (size_t)row * KK + tx * 8;
        *(float4*)&g_C[base]     = make_float4(c[0], c[1], c[2], c[3]);
        *(float4*)&g_C[base + 4] = make_float4(c[4], c[5], c[6], c[7]);
        *(float4*)&g_K[base]     = make_float4(kv[0], kv[1], kv[2], kv[3]);
        *(float4*)&g_K[base + 4] = make_float4(kv[4], kv[5], kv[6], kv[7]);
    }
}

// ---------------------------------------------------------------------------
// fused Sinkhorn iteration: w = nu'/T_prev ; a_i = mu'/(K' w)_i ; T_cur += K'^T a
// grid 512 x 256 threads; warp handles 16 rows; lane owns cols {4l..4l+3, 128+4l..}
// ---------------------------------------------------------------------------
__global__ void k_iter(int prev, int cur, int clr) {
    const float nuP = 1.f / (float)KK + 1e-8f;
    const float muP = 1.f / (float)BB + 1e-8f;
    __shared__ float Ts2[8 * 256];  // per-warp column partials

    int t = threadIdx.x, lane = t & 31, warp = t >> 5;
    if (blockIdx.x == 0) g_T[clr][t * 32] = 0.f;  // clear buffer for NEXT kernel

    float w[8];
#pragma unroll
    for (int m = 0; m < 4; m++) {
        w[m]     = nuP * __fdividef(1.f, g_T[prev][(lane * 4 + m) * 32]);
        w[4 + m] = nuP * __fdividef(1.f, g_T[prev][(128 + lane * 4 + m) * 32]);
    }

    float tj[8] = {0, 0, 0, 0, 0, 0, 0, 0};
    int rowBase = blockIdx.x * 128 + warp * 16;
#pragma unroll 2
    for (int r = 0; r < 16; r++) {
        int row = rowBase + r;
        const float4* Kr = (const float4*)(g_K + (size_t)row * KK);
        float4 k0 = Kr[lane];
        float4 k1 = Kr[32 + lane];
        float s = k0.x * w[0] + k0.y * w[1] + k0.z * w[2] + k0.w * w[3]
                + k1.x * w[4] + k1.y * w[5] + k1.z * w[6] + k1.w * w[7];
#pragma unroll
        for (int o = 16; o; o >>= 1) s += __shfl_xor_sync(0xffffffffu, s, o);
        float a = muP * __fdividef(1.f, s);
        if (lane == 0) g_a[row] = a;
        tj[0] += k0.x * a; tj[1] += k0.y * a; tj[2] += k0.z * a; tj[3] += k0.w * a;
        tj[4] += k1.x * a; tj[5] += k1.y * a; tj[6] += k1.z * a; tj[7] += k1.w * a;
    }

    // deterministic-per-block column reduction (no smem atomics)
#pragma unroll
    for (int m = 0; m < 4; m++) {
        Ts2[warp * 256 + lane * 4 + m] = tj[m];
        Ts2[warp * 256 + 128 + lane * 4 + m] = tj[4 + m];
    }
    __syncthreads();
    {   // t < 256: sum 8 warp partials for column t, one global atomic per column
        float s = 0.f;
#pragma unroll
        for (int ww = 0; ww < 8; ww++) s += Ts2[ww * 256 + t];
        atomicAdd(&g_T[cur][t * 32], s);
    }
}

// ---------------------------------------------------------------------------
// final: sum_ij a_i * K'_ij * w_j * C_ij * softmax(|coord_i|)_j
// ---------------------------------------------------------------------------
__global__ void k_final(const float* __restrict__ coord, int cur) {
    const float nuP = 1.f / (float)KK + 1e-8f;
    int t = threadIdx.x, lane = t & 31, warp = t >> 5;

    float w[8];
#pragma unroll
    for (int m = 0; m < 4; m++) {
        w[m]     = nuP * __fdividef(1.f, g_T[cur][(lane * 4 + m) * 32]);
        w[4 + m] = nuP * __fdividef(1.f, g_T[cur][(128 + lane * 4 + m) * 32]);
    }

    float accf = 0.f;
    int rowBase = blockIdx.x * 128 + warp * 16;
    for (int r = 0; r < 16; r++) {
        int row = rowBase + r;
        const float4* Cd = (const float4*)(coord + (size_t)row * KK);
        float4 c0 = Cd[lane], c1 = Cd[32 + lane];
        float q[8] = {fabsf(c0.x), fabsf(c0.y), fabsf(c0.z), fabsf(c0.w),
                      fabsf(c1.x), fabsf(c1.y), fabsf(c1.z), fabsf(c1.w)};
        float mx = q[0];
#pragma unroll
        for (int m = 1; m < 8; m++) mx = fmaxf(mx, q[m]);
#pragma unroll
        for (int o = 16; o; o >>= 1) mx = fmaxf(mx, __shfl_xor_sync(0xffffffffu, mx, o));
        float e[8], z = 0.f;
#pragma unroll
        for (int m = 0; m < 8; m++) { e[m] = __expf(q[m] - mx); z += e[m]; }
#pragma unroll
        for (int o = 16; o; o >>= 1) z += __shfl_xor_sync(0xffffffffu, z, o);
        float rz = __fdividef(1.f, z);

        float a = g_a[row];
        const float4* Kr = (const float4*)(g_K + (size_t)row * KK);
        const float4* Cr = (const float4*)(g_C + (size_t)row * KK);
        float4 k0 = Kr[lane], k1 = Kr[32 + lane];
        float4 cc0 = Cr[lane], cc1 = Cr[32 + lane];

        float contrib =
            k0.x * w[0] * cc0.x * e[0] + k0.y * w[1] * cc0.y * e[1] +
            k0.z * w[2] * cc0.z * e[2] + k0.w * w[3] * cc0.w * e[3] +
            k1.x * w[4] * cc1.x * e[4] + k1.y * w[5] * cc1.y * e[5] +
            k1.z * w[6] * cc1.z * e[6] + k1.w * w[7] * cc1.w * e[7];
        accf += a * rz * contrib;
    }

#pragma unroll
    for (int o = 16; o; o >>= 1) accf += __shfl_xor_sync(0xffffffffu, accf, o);
    __shared__ double sw[8];
    if (lane == 0) sw[warp] = (double)accf;
    __syncthreads();
    if (t == 0) {
        double s = 0.0;
#pragma unroll
        for (int i = 0; i < 8; i++) s += sw[i];
        atomicAdd(&g_sum, s);
    }
}

__global__ void k_write(float* out) { out[0] = (float)g_sum; }

// ---------------------------------------------------------------------------
extern "C" void kernel_launch(void* const* d_in, const int* in_sizes, int n_in,
                              void* d_out, int out_size) {
    const float* x     = (const float*)d_in[0];   // (65536, 128)
    const float* proto = (const float*)d_in[1];   // (256, 128)
    const float* coord = (const float*)d_in[2];   // (65536, 256)

    k_init<<<1, 256>>>(proto);
    k_xnorm<<<BB / 8, 256>>>(x);
    k_gemm<<<BB / 64, 256>>>(x);

    for (int it = 1; it <= 50; it++)
        k_iter<<<512, 256>>>((it - 1) % 3, it % 3, (it + 1) % 3);

    k_final<<<512, 256>>>(coord, 50 % 3);
    k_write<<<1, 1>>>((float*)d_out);
}